// round 1
// baseline (speedup 1.0000x reference)
#include <cuda_runtime.h>

// Exact integer reformulation of the PUMA crossbar MVM conv:
//  - ADC clip never binds (max analog sum 384 < 511), round is identity.
//  - Slice/stream shift-add recombines exactly to  xi16 . (wp - wn).
//  - So: out = RNE_clip( conv_int(xi16, dw) / 4096 ) / 4096, all exact in int32.

namespace {
constexpr int BATCH = 4, CIN = 64, H = 16, W = 16, COUT = 128;
constexpr int CO_CHUNK = 32;          // Cout per block
constexpr int CI_CHUNK = 16;          // Cin staged per SMEM phase
constexpr int KCH = CI_CHUNK * 9;     // 144 k-taps per phase
constexpr int SW_PITCH = CO_CHUNK + 4; // 36 ints -> 144B rows (16B aligned, low bank conflict)
constexpr int THREADS = 256;
}

__global__ __launch_bounds__(THREADS, 1)
void conv_mvm_kernel(const float* __restrict__ x,
                     const float* __restrict__ w,
                     float* __restrict__ out)
{
    __shared__ int sw[KCH * SW_PITCH];    // 20.7 KB: weights [k][co_local]
    __shared__ int sx[CI_CHUNK * 4 * 18]; // 4.6 KB : inputs  [ci][row 0..3][col -1..16]

    const int bid    = blockIdx.x;            // 128 blocks
    const int coBase = (bid & 3) * CO_CHUNK;  // 4 co chunks
    const int ohBase = ((bid >> 2) & 7) * 2;  // 8 pairs of output rows
    const int b      = bid >> 5;              // 4 batches

    const int tid   = threadIdx.x;
    const int ow    = tid & 15;
    const int cog   = (tid >> 4) & 7;  // group of 4 Cout
    const int ohsub = tid >> 7;        // which of the 2 output rows

    int acc0 = 0, acc1 = 0, acc2 = 0, acc3 = 0;

    for (int cc = 0; cc < CIN / CI_CHUNK; ++cc) {
        const int ciBase = cc * CI_CHUNK;

        // ---- stage weights: quantize on the fly, layout [k][co_local] ----
        #pragma unroll
        for (int it = 0; it < (KCH * CO_CHUNK) / THREADS; ++it) {
            int idx = it * THREADS + tid;
            int col = idx / KCH;              // co_local (coalesced gmem reads per col)
            int kl  = idx - col * KCH;        // tap within chunk
            float wv = w[(coBase + col) * (CIN * 9) + ciBase * 9 + kl];
            int q = (int)rintf(wv * 4096.0f); // == clip(rint(max(w,0)*4096)) - clip(rint(max(-w,0)*4096))
            q = max(-65535, min(65535, q));
            sw[kl * SW_PITCH + col] = q;
        }

        // ---- stage inputs: 16 ci x 4 rows x 18 cols, with zero padding ----
        for (int idx = tid; idx < CI_CHUNK * 4 * 18; idx += THREADS) {
            int col = idx % 18;
            int r   = (idx / 18) & 3;
            int cil = idx / 72;
            int gr  = ohBase - 1 + r;
            int gc  = col - 1;
            int v = 0;
            if ((unsigned)gr < (unsigned)H && (unsigned)gc < (unsigned)W) {
                float xv = x[((b * CIN + ciBase + cil) * H + gr) * W + gc];
                int xi = (int)rintf(xv * 4096.0f);
                v = (xi << 16) >> 16;   // 16-bit two's complement truncation (x_int & 0xFFFF, sign-extended)
            }
            sx[idx] = v;
        }
        __syncthreads();

        // ---- integer MAC mainloop: 144 taps x 4 Cout per thread ----
        #pragma unroll 2
        for (int cil = 0; cil < CI_CHUNK; ++cil) {
            const int* xr = &sx[cil * 72 + ohsub * 18];
            const int* wr = &sw[cil * 9 * SW_PITCH + cog * 4];
            #pragma unroll
            for (int ki = 0; ki < 3; ++ki) {
                int x0 = xr[ki * 18 + ow];
                int x1 = xr[ki * 18 + ow + 1];
                int x2 = xr[ki * 18 + ow + 2];
                int4 w0 = *(const int4*)&wr[(ki * 3 + 0) * SW_PITCH];
                int4 w1 = *(const int4*)&wr[(ki * 3 + 1) * SW_PITCH];
                int4 w2 = *(const int4*)&wr[(ki * 3 + 2) * SW_PITCH];
                acc0 += x0 * w0.x + x1 * w1.x + x2 * w2.x;
                acc1 += x0 * w0.y + x1 * w1.y + x2 * w2.y;
                acc2 += x0 * w0.z + x1 * w1.z + x2 * w2.z;
                acc3 += x0 * w0.w + x1 * w1.w + x2 * w2.w;
            }
        }
        __syncthreads();
    }

    // ---- epilogue: S/2^24 -> round-half-even to 1/4096 grid, clip to int16 range ----
    const int oh    = ohBase + ohsub;
    const int coOut = coBase + cog * 4;
    float* op = out + ((b * COUT + coOut) * H + oh) * W + ow;
    int accs[4] = {acc0, acc1, acc2, acc3};
    #pragma unroll
    for (int j = 0; j < 4; ++j) {
        int S    = accs[j];
        int base = S >> 12;               // floor(S/4096)
        int rem  = S - (base << 12);      // 0..4095
        if (rem > 2048)       base += 1;
        else if (rem == 2048) base += (base & 1);   // ties to even
        base = max(-32768, min(32767, base));
        op[j * (H * W)] = (float)base * (1.0f / 4096.0f);
    }
}

extern "C" void kernel_launch(void* const* d_in, const int* in_sizes, int n_in,
                              void* d_out, int out_size) {
    const float* x = (const float*)d_in[0];
    const float* w = (const float*)d_in[1];
    // defensive: identify tensors by element count (x: 4*64*16*16 = 65536, w: 128*64*9 = 73728)
    if (n_in >= 2 && in_sizes[0] == 73728 && in_sizes[1] == 65536) {
        x = (const float*)d_in[1];
        w = (const float*)d_in[0];
    }
    conv_mvm_kernel<<<128, THREADS>>>(x, w, (float*)d_out);
}